// round 1
// baseline (speedup 1.0000x reference)
#include <cuda_runtime.h>
#include <cstdint>

#define Bb 32
#define Cc 32
#define Tt 2048
#define Dd 512
#define ALPHA 0.1f
#define BETA  0.9f

// Scratch (no cudaMalloc allowed)
__device__ float g_sA[Bb*Cc*Tt];      // 0.5 * forward EWMA of diff   [b][c][t]
__device__ float g_sB[Bb*Cc*Tt];      // 0.5 * backward EWMA of diff  [b][c][t]
__device__ float g_wcomb[Dd*Cc];      // (W_lin @ W_ve)[e][c]
__device__ float g_bcomb[Dd];         // W_lin @ b_ve + b_lin

// ---------------------------------------------------------------------------
// P: compose the two linear layers.  Wcomb[e,c] = sum_d W_lin[e,d]*W_ve[d,c]
// ---------------------------------------------------------------------------
__global__ void __launch_bounds__(256) prep_kernel(
    const float* __restrict__ W_ve, const float* __restrict__ b_ve,
    const float* __restrict__ W_lin, const float* __restrict__ b_lin)
{
    int idx = blockIdx.x * blockDim.x + threadIdx.x;
    if (idx >= Dd * (Cc + 1)) return;
    int e = idx / (Cc + 1);
    int c = idx % (Cc + 1);
    const float* wl = W_lin + (size_t)e * Dd;
    float acc = 0.f;
    if (c < Cc) {
        #pragma unroll 8
        for (int d = 0; d < Dd; d++) acc = fmaf(wl[d], W_ve[d * Cc + c], acc);
        g_wcomb[e * Cc + c] = acc;
    } else {
        #pragma unroll 8
        for (int d = 0; d < Dd; d++) acc = fmaf(wl[d], b_ve[d], acc);
        g_bcomb[e] = acc + b_lin[e];
    }
}

// ---------------------------------------------------------------------------
// S: bidirectional EWMA of the first-difference, per (b,c) row of x[B,C,T].
// One warp per (row, direction). Kogge-Stone scan for c_t = a*d_t + b*c_{t-1}
// with constant b: combine factor at offset s is BETA^s.
// Forward init: d_0 = 0 so f_0 = 0 == standard recurrence with carry 0.
// Backward init: g_{T-1} = d_{T-1}; since BETA = 1-ALPHA, standard recurrence
// with carry = d_{T-1} reproduces it exactly.
// ---------------------------------------------------------------------------
__global__ void __launch_bounds__(256) scan_kernel(const float* __restrict__ x)
{
    const unsigned FULL = 0xffffffffu;
    int gwarp = (blockIdx.x * blockDim.x + threadIdx.x) >> 5;
    int lane  = threadIdx.x & 31;
    bool bwd  = gwarp >= Bb * Cc;
    int  bc   = bwd ? (gwarp - Bb * Cc) : gwarp;
    if (bc >= Bb * Cc) return;

    const float* row  = x + (size_t)bc * Tt;
    float*       srow = (bwd ? g_sB : g_sA) + (size_t)bc * Tt;

    const float b1 = BETA;
    const float b2 = b1 * b1;
    const float b4 = b2 * b2;
    const float b8 = b4 * b4;
    const float b16 = b8 * b8;

    // BETA^(lane+1) by repeated squaring
    float blp1;
    {
        float p = 1.f, base = BETA;
        int n = lane + 1;
        while (n) { if (n & 1) p *= base; base *= base; n >>= 1; }
        blp1 = p;
    }

    float carry = bwd ? (row[Tt - 1] - row[Tt - 2]) : 0.f;

    for (int k = 0; k < 64; k++) {
        int t = bwd ? (Tt - 1 - k * 32 - lane) : (k * 32 + lane);
        float y = row[t];
        float d = (t == 0) ? 0.f : (y - row[t - 1]);
        float A = ALPHA * d;
        float Ao;
        Ao = __shfl_up_sync(FULL, A, 1);  if (lane >= 1)  A = fmaf(b1,  Ao, A);
        Ao = __shfl_up_sync(FULL, A, 2);  if (lane >= 2)  A = fmaf(b2,  Ao, A);
        Ao = __shfl_up_sync(FULL, A, 4);  if (lane >= 4)  A = fmaf(b4,  Ao, A);
        Ao = __shfl_up_sync(FULL, A, 8);  if (lane >= 8)  A = fmaf(b8,  Ao, A);
        Ao = __shfl_up_sync(FULL, A, 16); if (lane >= 16) A = fmaf(b16, Ao, A);
        float f = fmaf(blp1, carry, A);
        srow[t] = 0.5f * f;
        carry = __shfl_sync(FULL, f, 31);
    }
}

// ---------------------------------------------------------------------------
// G: out[b,t,e] = sum_c (sA+sB)[b,c,t] * Wcomb[e,c] + bcomb[e]
// Tile: 32 t  x  128 e per block. Block 32x8 threads, 4t x 4e per thread.
// ---------------------------------------------------------------------------
__global__ void __launch_bounds__(256) gemm_kernel(float* __restrict__ out)
{
    __shared__ float ssm[Cc][36];    // [c][t_local], row stride 144B (16B-mult)
    __shared__ float wsm[Cc][132];   // [c][e_local], row stride 528B (16B-mult)

    int tx = threadIdx.x;            // 0..31 -> e
    int ty = threadIdx.y;            // 0..7  -> t
    int tid = ty * 32 + tx;
    int b = blockIdx.z;
    int tBase = blockIdx.x * 32;
    int eBase = blockIdx.y * 128;

    // Load s tile: 32c x 32t, summing fwd + bwd halves (both 0.5-scaled).
    {
        int c  = tid >> 3;
        int tl = (tid & 7) * 4;
        size_t off = ((size_t)(b * Cc + c)) * Tt + tBase + tl;
        float4 a  = *(const float4*)(g_sA + off);
        float4 bq = *(const float4*)(g_sB + off);
        ssm[c][tl + 0] = a.x + bq.x;
        ssm[c][tl + 1] = a.y + bq.y;
        ssm[c][tl + 2] = a.z + bq.z;
        ssm[c][tl + 3] = a.w + bq.w;
    }
    // Load W tile: 128e x 32c, transposed to [c][e].
    #pragma unroll
    for (int r = 0; r < 4; r++) {
        int idx = tid + r * 256;         // 0..1023
        int el = idx >> 3;               // 0..127
        int c4 = (idx & 7) * 4;
        float4 w = *(const float4*)(g_wcomb + (size_t)(eBase + el) * Cc + c4);
        wsm[c4 + 0][el] = w.x;
        wsm[c4 + 1][el] = w.y;
        wsm[c4 + 2][el] = w.z;
        wsm[c4 + 3][el] = w.w;
    }
    __syncthreads();

    float acc[4][4];
    #pragma unroll
    for (int i = 0; i < 4; i++)
        #pragma unroll
        for (int j = 0; j < 4; j++) acc[i][j] = 0.f;

    #pragma unroll
    for (int c = 0; c < Cc; c++) {
        float4 s4 = *(const float4*)&ssm[c][ty * 4];
        float4 w4 = *(const float4*)&wsm[c][tx * 4];
        float sv[4] = {s4.x, s4.y, s4.z, s4.w};
        float wv[4] = {w4.x, w4.y, w4.z, w4.w};
        #pragma unroll
        for (int i = 0; i < 4; i++)
            #pragma unroll
            for (int j = 0; j < 4; j++)
                acc[i][j] = fmaf(sv[i], wv[j], acc[i][j]);
    }

    float4 bias = *(const float4*)(g_bcomb + eBase + tx * 4);
    #pragma unroll
    for (int i = 0; i < 4; i++) {
        int t = tBase + ty * 4 + i;
        float4 o;
        o.x = acc[i][0] + bias.x;
        o.y = acc[i][1] + bias.y;
        o.z = acc[i][2] + bias.z;
        o.w = acc[i][3] + bias.w;
        *(float4*)(out + ((size_t)(b * Tt + t)) * Dd + eBase + tx * 4) = o;
    }
}

// ---------------------------------------------------------------------------
extern "C" void kernel_launch(void* const* d_in, const int* in_sizes, int n_in,
                              void* d_out, int out_size)
{
    const float* x     = (const float*)d_in[0];   // [B, C, T]
    const float* W_ve  = (const float*)d_in[1];   // [D, C]
    const float* b_ve  = (const float*)d_in[2];   // [D]
    const float* W_lin = (const float*)d_in[3];   // [D, D]
    const float* b_lin = (const float*)d_in[4];   // [D]
    float* out = (float*)d_out;                   // [B, T, D]

    // P: compose linears (independent of S; same stream keeps order for G)
    prep_kernel<<<(Dd * (Cc + 1) + 255) / 256, 256>>>(W_ve, b_ve, W_lin, b_lin);

    // S: 2048 scan warps (1024 fwd + 1024 bwd), 8 warps/block
    scan_kernel<<<(2 * Bb * Cc * 32) / 256, 256>>>(x);

    // G: final K=32 GEMM + bias
    dim3 grid(Tt / 32, Dd / 128, Bb);
    dim3 block(32, 8);
    gemm_kernel<<<grid, block>>>(out);
}

// round 2
// speedup vs baseline: 1.1783x; 1.1783x over previous
#include <cuda_runtime.h>
#include <cstdint>

#define Bb 32
#define Cc 32
#define Tt 2048
#define Dd 512
#define ALPHA 0.1f
#define BETA  0.9f

#define SEG   256      // scan segment length
#define WARM  160      // truncated history (beta^160 ~ 5e-8)
#define NSEG  (Tt / SEG)

// Scratch (no cudaMalloc allowed)
__device__ float g_sA[Bb*Cc*Tt];      // 0.5 * forward EWMA of diff   [b][c][t]
__device__ float g_sB[Bb*Cc*Tt];      // 0.5 * backward EWMA of diff  [b][c][t]
__device__ float g_wcomb[Dd*Cc];      // (W_lin @ W_ve)[e][c]
__device__ float g_bcomb[Dd];         // W_lin @ b_ve + b_lin

// ---------------------------------------------------------------------------
// P: compose linears. One block per output row e. 8 warps; warp j handles
// columns c = j, j+8, ... (c==32 -> bias). Lanes split d, 5-shfl reduce.
// ---------------------------------------------------------------------------
__global__ void __launch_bounds__(256) prep_kernel(
    const float* __restrict__ W_ve, const float* __restrict__ b_ve,
    const float* __restrict__ W_lin, const float* __restrict__ b_lin)
{
    __shared__ float wl[Dd];
    int e = blockIdx.x;
    int tid = threadIdx.x;
    wl[tid]       = W_lin[(size_t)e * Dd + tid];
    wl[tid + 256] = W_lin[(size_t)e * Dd + tid + 256];
    __syncthreads();

    int wj   = tid >> 5;
    int lane = tid & 31;
    const unsigned FULL = 0xffffffffu;

    for (int c = wj; c <= Cc; c += 8) {
        float acc = 0.f;
        if (c < Cc) {
            #pragma unroll
            for (int i = 0; i < 16; i++) {
                int d = lane + 32 * i;
                acc = fmaf(wl[d], W_ve[d * Cc + c], acc);
            }
        } else {
            #pragma unroll
            for (int i = 0; i < 16; i++) {
                int d = lane + 32 * i;
                acc = fmaf(wl[d], b_ve[d], acc);
            }
        }
        acc += __shfl_down_sync(FULL, acc, 16);
        acc += __shfl_down_sync(FULL, acc, 8);
        acc += __shfl_down_sync(FULL, acc, 4);
        acc += __shfl_down_sync(FULL, acc, 2);
        acc += __shfl_down_sync(FULL, acc, 1);
        if (lane == 0) {
            if (c < Cc) g_wcomb[e * Cc + c] = acc;
            else        g_bcomb[e] = acc + b_lin[e];
        }
    }
}

// ---------------------------------------------------------------------------
// S: bidirectional EWMA of first-difference, segment-parallel with truncated
// warm-up. One warp per (row, segment, direction). Kogge-Stone within chunks
// of 32; constant-coefficient combine factors are powers of BETA.
// ---------------------------------------------------------------------------
__global__ void __launch_bounds__(256) scan_kernel(const float* __restrict__ x)
{
    const unsigned FULL = 0xffffffffu;
    int g    = blockIdx.x * 8 + (threadIdx.x >> 5);   // global warp id
    int lane = threadIdx.x & 31;
    int bc   = g >> 4;           // row index (b*Cc + c)
    int rem  = g & 15;
    int seg  = rem >> 1;
    int dir  = rem & 1;          // 0 = fwd, 1 = bwd

    const float* row = x + (size_t)bc * Tt;

    const float b1 = BETA;
    const float b2 = b1 * b1;
    const float b4 = b2 * b2;
    const float b8 = b4 * b4;
    const float b16 = b8 * b8;

    // BETA^(lane+1)
    float blp1;
    {
        float p = 1.f, base = BETA;
        int n = lane + 1;
        while (n) { if (n & 1) p *= base; base *= base; n >>= 1; }
        blp1 = p;
    }

    int lo = seg * SEG;
    int hi = lo + SEG;

    if (dir == 0) {
        float* srow = g_sA + (size_t)bc * Tt;
        int start = (seg == 0) ? 0 : (lo - WARM);
        float carry = 0.f;
        for (int t0 = start; t0 < hi; t0 += 32) {
            int t = t0 + lane;
            float y = row[t];
            float d = (t == 0) ? 0.f : (y - row[t - 1]);
            float A = ALPHA * d;
            float Ao;
            Ao = __shfl_up_sync(FULL, A, 1);  if (lane >= 1)  A = fmaf(b1,  Ao, A);
            Ao = __shfl_up_sync(FULL, A, 2);  if (lane >= 2)  A = fmaf(b2,  Ao, A);
            Ao = __shfl_up_sync(FULL, A, 4);  if (lane >= 4)  A = fmaf(b4,  Ao, A);
            Ao = __shfl_up_sync(FULL, A, 8);  if (lane >= 8)  A = fmaf(b8,  Ao, A);
            Ao = __shfl_up_sync(FULL, A, 16); if (lane >= 16) A = fmaf(b16, Ao, A);
            float f = fmaf(blp1, carry, A);
            if (t0 >= lo) srow[t] = 0.5f * f;
            carry = __shfl_sync(FULL, f, 31);
        }
    } else {
        float* srow = g_sB + (size_t)bc * Tt;
        bool last = (hi == Tt);
        int top = last ? (Tt - 1) : (hi - 1 + WARM);
        // exact init at right boundary: with carry=d_{T-1}, lane0 at t=T-1
        // yields alpha*d + beta*d = d  (since beta = 1-alpha)
        float carry = last ? (row[Tt - 1] - row[Tt - 2]) : 0.f;
        for (int tb = top; tb >= lo + 31; tb -= 32) {
            int t = tb - lane;                 // descending t with lane
            float y = row[t];
            float d = (t == 0) ? 0.f : (y - row[t - 1]);
            float A = ALPHA * d;
            float Ao;
            Ao = __shfl_up_sync(FULL, A, 1);  if (lane >= 1)  A = fmaf(b1,  Ao, A);
            Ao = __shfl_up_sync(FULL, A, 2);  if (lane >= 2)  A = fmaf(b2,  Ao, A);
            Ao = __shfl_up_sync(FULL, A, 4);  if (lane >= 4)  A = fmaf(b4,  Ao, A);
            Ao = __shfl_up_sync(FULL, A, 8);  if (lane >= 8)  A = fmaf(b8,  Ao, A);
            Ao = __shfl_up_sync(FULL, A, 16); if (lane >= 16) A = fmaf(b16, Ao, A);
            float f = fmaf(blp1, carry, A);
            if (tb < hi) srow[t] = 0.5f * f;
            carry = __shfl_sync(FULL, f, 31);
        }
    }
}

// ---------------------------------------------------------------------------
// G: out[b,t,e] = sum_c (sA+sB)[b,c,t] * Wcomb[e,c] + bcomb[e]
// Block tile: 64 t x 512 e (looped in 4 chunks of 128 e). 256 threads,
// 8t x 4e per thread per chunk. ssm loaded once, reused across all e.
// ---------------------------------------------------------------------------
__global__ void __launch_bounds__(256) gemm_kernel(float* __restrict__ out)
{
    __shared__ float ssm[Cc][68];    // [c][t_local], 272B rows
    __shared__ float wsm[Cc][132];   // [c][e_local], 528B rows

    int tx = threadIdx.x & 31;       // -> e (4 each)
    int ty = threadIdx.x >> 5;       // -> t (8 each)
    int tid = threadIdx.x;
    int b = blockIdx.y;
    int tBase = blockIdx.x * 64;

    // Load s tile: 32c x 64t, summing fwd + bwd halves (both 0.5-scaled).
    #pragma unroll
    for (int r = 0; r < 2; r++) {
        int idx = tid + r * 256;         // 0..511
        int c   = idx >> 4;              // 0..31
        int tl  = (idx & 15) * 4;        // 0..60
        size_t off = ((size_t)(b * Cc + c)) * Tt + tBase + tl;
        float4 a  = *(const float4*)(g_sA + off);
        float4 bq = *(const float4*)(g_sB + off);
        ssm[c][tl + 0] = a.x + bq.x;
        ssm[c][tl + 1] = a.y + bq.y;
        ssm[c][tl + 2] = a.z + bq.z;
        ssm[c][tl + 3] = a.w + bq.w;
    }

    for (int ch = 0; ch < 4; ch++) {
        int eBase = ch * 128;
        __syncthreads();   // protect wsm (prev chunk readers) & first-iter ssm
        #pragma unroll
        for (int r = 0; r < 4; r++) {
            int idx = tid + r * 256;     // 0..1023
            int el  = idx >> 3;          // 0..127
            int c4  = (idx & 7) * 4;
            float4 w = *(const float4*)(g_wcomb + (size_t)(eBase + el) * Cc + c4);
            wsm[c4 + 0][el] = w.x;
            wsm[c4 + 1][el] = w.y;
            wsm[c4 + 2][el] = w.z;
            wsm[c4 + 3][el] = w.w;
        }
        __syncthreads();

        float acc[8][4];
        #pragma unroll
        for (int i = 0; i < 8; i++)
            #pragma unroll
            for (int j = 0; j < 4; j++) acc[i][j] = 0.f;

        #pragma unroll
        for (int c = 0; c < Cc; c++) {
            float4 s0 = *(const float4*)&ssm[c][ty * 8];
            float4 s1 = *(const float4*)&ssm[c][ty * 8 + 4];
            float4 w4 = *(const float4*)&wsm[c][tx * 4];
            float sv[8] = {s0.x, s0.y, s0.z, s0.w, s1.x, s1.y, s1.z, s1.w};
            float wv[4] = {w4.x, w4.y, w4.z, w4.w};
            #pragma unroll
            for (int i = 0; i < 8; i++)
                #pragma unroll
                for (int j = 0; j < 4; j++)
                    acc[i][j] = fmaf(sv[i], wv[j], acc[i][j]);
        }

        float4 bias = *(const float4*)(g_bcomb + eBase + tx * 4);
        #pragma unroll
        for (int i = 0; i < 8; i++) {
            int t = tBase + ty * 8 + i;
            float4 o;
            o.x = acc[i][0] + bias.x;
            o.y = acc[i][1] + bias.y;
            o.z = acc[i][2] + bias.z;
            o.w = acc[i][3] + bias.w;
            *(float4*)(out + ((size_t)(b * Tt + t)) * Dd + eBase + tx * 4) = o;
        }
    }
}

// ---------------------------------------------------------------------------
extern "C" void kernel_launch(void* const* d_in, const int* in_sizes, int n_in,
                              void* d_out, int out_size)
{
    const float* x     = (const float*)d_in[0];   // [B, C, T]
    const float* W_ve  = (const float*)d_in[1];   // [D, C]
    const float* b_ve  = (const float*)d_in[2];   // [D]
    const float* W_lin = (const float*)d_in[3];   // [D, D]
    const float* b_lin = (const float*)d_in[4];   // [D]
    float* out = (float*)d_out;                   // [B, T, D]

    // S: 16384 segment-warps (rows x 8 segs x 2 dirs), 8 warps/block
    scan_kernel<<<(Bb * Cc * NSEG * 2) / 8, 256>>>(x);

    // P: compose linears (independent of S; same-stream order feeds G)
    prep_kernel<<<Dd, 256>>>(W_ve, b_ve, W_lin, b_lin);

    // G: final K=32 GEMM + bias
    dim3 grid(Tt / 64, Bb);
    gemm_kernel<<<grid, 256>>>(out);
}